// round 15
// baseline (speedup 1.0000x reference)
#include <cuda_runtime.h>
#include <cuda_fp16.h>
#include <cstdint>

// Problem constants
#define BB 32
#define SS 2048
#define DD 1024
#define UU 1024
#define BS (BB*SS)            // 65536 tokens

// Output layout: context [B,D] | attn [B,S] | coverage [B,S]
#define CTX_OFF 0
#define ATTN_OFF (BB*DD)
#define COV_OFF  (BB*DD + BB*SS)

// GEMM tiling
#define BM 256
#define BN 128
#define BKH 64                         // K-chunk in halves (128B rows)
#define KSTAGES 16                     // DD / BKH
#define NTILES 2048                    // (BS/BM) * (UU/BN)
#define NMT 256                        // number of m-tiles (BS/BM)
#define A_BLK_H 16384                  // halves per A tile block (256*64) = 32KB
#define B_BLK_H 8192                   // halves per B tile block (128*64) = 16KB

// Device scratch (allocation-free rule: __device__ globals)
__device__ float  g_hbias[BB*UU];          // dec@Wh + Wh_b + Ws_b + Wc_b
__device__ float  g_score[BS];             // pre-softmax scores
__device__ __half g_Xh[(size_t)BS*DD];     // enc_output fp16, tile-blocked+swizzled
__device__ __half g_Wth[UU*DD];            // Ws_w^T fp16, tile-blocked+swizzled
__device__ int    g_cnt[NMT];              // per-m-tile convert completion (0-init; reset by softmax)

// ---------------------------------------------------------------------------
// helpers
// ---------------------------------------------------------------------------
__device__ __forceinline__ uint32_t smem_u32(const void* p) {
    uint32_t a;
    asm("{ .reg .u64 t; cvta.to.shared.u64 t, %1; cvt.u32.u64 %0, t; }"
        : "=r"(a) : "l"(p));
    return a;
}

__device__ __forceinline__ void mbar_init(uint32_t addr, uint32_t cnt) {
    asm volatile("mbarrier.init.shared.b64 [%0], %1;" :: "r"(addr), "r"(cnt) : "memory");
}

__device__ __forceinline__ void mbar_expect_tx(uint32_t addr, uint32_t bytes) {
    asm volatile("mbarrier.arrive.expect_tx.shared.b64 _, [%0], %1;"
                 :: "r"(addr), "r"(bytes) : "memory");
}

__device__ __forceinline__ void mbar_arrive(uint32_t addr) {
    asm volatile("mbarrier.arrive.shared.b64 _, [%0];" :: "r"(addr) : "memory");
}

__device__ __forceinline__ void mbar_wait(uint32_t addr, uint32_t parity) {
    asm volatile(
        "{\n\t.reg .pred P;\n"
        "WAIT_%=: \n\t"
        "mbarrier.try_wait.parity.acquire.cta.shared::cta.b64 P, [%0], %1, 0x989680;\n\t"
        "@P bra DONE_%=;\n\t"
        "bra WAIT_%=;\n"
        "DONE_%=: \n\t}"
        :: "r"(addr), "r"(parity) : "memory");
}

__device__ __forceinline__ void bulk_ld(uint32_t sdst, const void* gsrc,
                                        uint32_t bytes, uint32_t mbar) {
    asm volatile(
        "cp.async.bulk.shared::cta.global.mbarrier::complete_tx::bytes "
        "[%0], [%1], %2, [%3];"
        :: "r"(sdst), "l"(gsrc), "r"(bytes), "r"(mbar) : "memory");
}

__device__ __forceinline__ void fence_proxy_async_cta() {
    asm volatile("fence.proxy.async.shared::cta;" ::: "memory");
}

__device__ __forceinline__ void ldsm4(uint32_t* r, uint32_t addr) {
    asm volatile("ldmatrix.sync.aligned.m8n8.x4.shared.b16 {%0,%1,%2,%3}, [%4];"
                 : "=r"(r[0]), "=r"(r[1]), "=r"(r[2]), "=r"(r[3]) : "r"(addr));
}

__device__ __forceinline__ void mma_f16(float* d, const uint32_t* a, const uint32_t* b) {
    asm volatile(
        "mma.sync.aligned.m16n8k16.row.col.f32.f16.f16.f32 "
        "{%0,%1,%2,%3}, {%4,%5,%6,%7}, {%8,%9}, {%0,%1,%2,%3};\n"
        : "+f"(d[0]), "+f"(d[1]), "+f"(d[2]), "+f"(d[3])
        : "r"(a[0]), "r"(a[1]), "r"(a[2]), "r"(a[3]),
          "r"(b[0]), "r"(b[1]));
}

__device__ __forceinline__ float fast_tanh(float x) {
    float t;
    asm("tanh.approx.f32 %0, %1;" : "=f"(t) : "f"(x));
    return t;
}

// ---------------------------------------------------------------------------
// Kernel W: transpose+convert Ws (blocks [0,1024)) + hbias/score0 ([1024,1088))
// ---------------------------------------------------------------------------
__global__ void __launch_bounds__(512)
prep_w_kernel(const float* __restrict__ W,
              const float* __restrict__ dec,
              const float* __restrict__ Whw,
              const float* __restrict__ Whb,
              const float* __restrict__ Wsb,
              const float* __restrict__ Wcb) {
    __shared__ float sbuf[1184];
    const int bid = blockIdx.x;
    const int tid = threadIdx.x;

    if (bid < 1024) {
        float (*t)[33] = (float(*)[33])sbuf;
        const int tx = tid & 31, ty = tid >> 5;          // ty 0..15
        const int bx = (bid & 31) * 32;                   // u base
        const int by = (bid >> 5) * 32;                   // d base
        #pragma unroll
        for (int j = 0; j < 2; j++)
            t[ty + j * 16][tx] = W[(size_t)(by + ty + j * 16) * UU + bx + tx];
        __syncthreads();
        #pragma unroll
        for (int j = 0; j < 2; j++) {
            const int u = bx + ty + j * 16;
            const int d = by + tx;
            const int nt = u >> 7, rowB = u & 127;
            const int kt = d >> 6, ch = (d & 63) >> 3, pos = d & 7;
            char* blk = (char*)(g_Wth + ((size_t)nt * KSTAGES + kt) * B_BLK_H);
            *(__half*)(blk + (rowB << 7) + ((ch ^ (rowB & 7)) << 4) + pos * 2) =
                __float2half(t[tx][ty + j * 16]);
        }
    } else {
        float* dh = sbuf;
        const int lb = bid - 1024;
        const int b = lb >> 1;
        const int u = (lb & 1) * 512 + tid;
        dh[tid] = dec[b * DD + tid];
        dh[tid + 512] = dec[b * DD + tid + 512];
        __syncthreads();

        float a0 = 0.f, a1 = 0.f, a2 = 0.f, a3 = 0.f;
        #pragma unroll 4
        for (int d = 0; d < DD; d += 4) {
            a0 += dh[d+0] * Whw[(size_t)(d+0)*UU + u];
            a1 += dh[d+1] * Whw[(size_t)(d+1)*UU + u];
            a2 += dh[d+2] * Whw[(size_t)(d+2)*UU + u];
            a3 += dh[d+3] * Whw[(size_t)(d+3)*UU + u];
        }
        g_hbias[b*UU + u] = (a0 + a1) + (a2 + a3) + Whb[u] + Wsb[u] + Wcb[u];

        const int gid = lb * 512 + tid;
        g_score[gid] = 0.f;
        g_score[gid + 32768] = 0.f;
    }
}

// ---------------------------------------------------------------------------
// Kernel X: convert enc fp32 -> fp16 tile-blocked swizzled (forked stream).
// Each block covers 4 token rows (all 16 kt blocks); 64 blocks per m-tile.
// Completion: threadfence + atomicAdd(g_cnt[mt]); GEMM spins to 64.
// grid 16384 x 512.
// ---------------------------------------------------------------------------
__global__ void __launch_bounds__(512)
convert_x_kernel(const float* __restrict__ X) {
    const int bid = blockIdx.x;
    const int tid = threadIdx.x;
    const size_t i = (size_t)bid * 512 + tid;
    const int m  = (int)(i >> 7);       // token row
    const int cg = (int)(i & 127);      // chunk-in-row
    const int kt = cg >> 3;
    const int ch = cg & 7;
    const int mt = m >> 8;
    const int row = m & 255;

    const float4* src = (const float4*)(X + (size_t)m * DD + kt * 64 + ch * 8);
    const float4 f0 = src[0];
    const float4 f1 = src[1];
    __half2 h0 = __float22half2_rn(make_float2(f0.x, f0.y));
    __half2 h1 = __float22half2_rn(make_float2(f0.z, f0.w));
    __half2 h2 = __float22half2_rn(make_float2(f1.x, f1.y));
    __half2 h3 = __float22half2_rn(make_float2(f1.z, f1.w));
    uint4 o;
    o.x = *(uint32_t*)&h0; o.y = *(uint32_t*)&h1;
    o.z = *(uint32_t*)&h2; o.w = *(uint32_t*)&h3;

    char* blk = (char*)(g_Xh + ((size_t)mt * KSTAGES + kt) * A_BLK_H);
    *(uint4*)(blk + (row << 7) + ((ch ^ (row & 7)) << 4)) = o;

    __syncthreads();
    if (tid == 0) {
        __threadfence();                       // writes visible at L2 before count
        atomicAdd(&g_cnt[bid >> 6], 1);        // mt = bid>>6 (4 rows/block)
    }
}

// ---------------------------------------------------------------------------
// Kernel B: PERSISTENT fp16 mma.sync fused score GEMM.
// grid = #SMs; pipeline runs continuously across tile boundaries.
// Producer spins on g_cnt[mt]==64 before bulk-loading a new m-tile's A data
// (conversion runs concurrently on a forked stream).
// ---------------------------------------------------------------------------
#define NST 4
#define STG 49152                      // 32KB A + 16KB B
#define STG_A 32768
#define OFF_SMALL (NST*STG)            // 196608; 2 x 640 floats
#define OFF_MBAR  (OFF_SMALL + 5120)   // 4 full mbarriers
#define OFF_MBARE (OFF_MBAR + 32)      // 4 empty mbarriers
#define SMEM_NEED (OFF_MBARE + 32)     // 201792

__global__ void __launch_bounds__(512, 1)
score_gemm_fp16(const float* __restrict__ Wcw,
                const float* __restrict__ Vw,
                const float* __restrict__ cov) {
    extern __shared__ char sm[];
    const int tid  = threadIdx.x;
    const int lane = tid & 31;
    const int wid  = tid >> 5;
    const int wm   = wid >> 2;        // 0..3
    const int wn   = wid & 3;         // 0..3
    const int r    = lane >> 2;       // 0..7
    const int c    = lane & 3;        // 0..3

    const uint32_t sbase = smem_u32(sm);
    const uint32_t mbF   = sbase + OFF_MBAR;
    const uint32_t mbE   = sbase + OFF_MBARE;
    const int grid = gridDim.x;
    const int ntiles = (NTILES - blockIdx.x + grid - 1) / grid;
    const int total_gs = ntiles * KSTAGES;

    if (tid == 0) {
        #pragma unroll
        for (int p = 0; p < NST; p++) {
            mbar_init(mbF + p * 8, 1);    // full: tx-based
            mbar_init(mbE + p * 8, 16);   // empty: one arrive per warp
        }
    }

    float* small0 = (float*)(sm + OFF_SMALL);

    {
        const int t0 = blockIdx.x;
        const int m0 = (t0 >> 3) * BM, n0 = (t0 & 7) * BN, b = m0 >> 11;
        if (tid < 128) {
            small0[tid]       = g_hbias[b * UU + n0 + tid];
            small0[128 + tid] = Wcw[n0 + tid];
            small0[256 + tid] = Vw[n0 + tid];
        } else if (tid < 384) {
            small0[384 + tid - 128] = cov[m0 + tid - 128];
        }
    }
    __syncthreads();
    fence_proxy_async_cta();

    int last_mt = -1;   // producer-thread cache of last ready m-tile

    if (tid == 0) {
        const int t0 = blockIdx.x;
        const int mt0 = t0 >> 3;
        // wait for this m-tile's conversion (concurrent stream)
        while (((volatile int*)g_cnt)[mt0] < 64) {}
        last_mt = mt0;
        const __half* Ab = g_Xh  + (size_t)mt0 * KSTAGES * A_BLK_H;
        const __half* Bb = g_Wth + (size_t)(t0 & 7) * KSTAGES * B_BLK_H;
        #pragma unroll
        for (int p = 0; p < 3; p++) {
            mbar_expect_tx(mbF + p * 8, STG);
            bulk_ld(sbase + p * STG,         Ab + (size_t)p * A_BLK_H, STG_A, mbF + p * 8);
            bulk_ld(sbase + p * STG + STG_A, Bb + (size_t)p * B_BLK_H, STG - STG_A, mbF + p * 8);
        }
    }

    const uint32_t slane = lane & 7;
    const uint32_t ahi   = lane >> 4;
    const uint32_t bbit  = (lane >> 3) & 1;
    uint32_t arow_off[4], brow_off[2];
    #pragma unroll
    for (int mi = 0; mi < 4; mi++)
        arow_off[mi] = (uint32_t)((wm * 64 + mi * 16 + (lane & 15)) << 7);
    #pragma unroll
    for (int njp = 0; njp < 2; njp++)
        brow_off[njp] = (uint32_t)(((wn * 32 + njp * 16 + slane + (ahi << 3)) << 7)
                                   + STG_A);

    #define LOAD_FRAGS(ST_, KK_, AF_, BF_) do {                               \
        const uint32_t xa_ = ((((KK_) << 1) + ahi)  ^ slane) << 4;            \
        const uint32_t xb_ = ((((KK_) << 1) + bbit) ^ slane) << 4;            \
        _Pragma("unroll")                                                     \
        for (int mi_ = 0; mi_ < 4; mi_++)                                     \
            ldsm4(AF_[mi_], (ST_) + arow_off[mi_] + xa_);                     \
        _Pragma("unroll")                                                     \
        for (int nj_ = 0; nj_ < 2; nj_++)                                     \
            ldsm4(BF_[nj_], (ST_) + brow_off[nj_] + xb_);                     \
    } while (0)

    int gs = 0;
    for (int tt = 0; tt < ntiles; tt++) {
        const int tile = blockIdx.x + tt * grid;
        const int m0 = (tile >> 3) * BM;
        const int n0 = (tile & 7) * BN;
        const int b  = m0 >> 11;
        float* sa = small0 + (tt & 1) * 640;

        if (tt > 0) {
            if (tid < 128) {
                sa[tid]       = g_hbias[b * UU + n0 + tid];
                sa[128 + tid] = Wcw[n0 + tid];
                sa[256 + tid] = Vw[n0 + tid];
            } else if (tid < 384) {
                sa[384 + tid - 128] = cov[m0 + tid - 128];
            }
        }

        float acc[4][4][4] = {};

        for (int s = 0; s < KSTAGES; s++, gs++) {
            if (tid == 0) {
                const int fgs = gs + 3;
                if (fgs < total_gs) {
                    const int p = fgs & 3;
                    if (gs >= 1)
                        mbar_wait(mbE + p * 8, (uint32_t)(((gs - 1) >> 2) & 1));
                    const int ft = blockIdx.x + (fgs >> 4) * grid;
                    const int mtf = ft >> 3;
                    if (mtf != last_mt) {        // new m-tile: ensure converted
                        while (((volatile int*)g_cnt)[mtf] < 64) {}
                        last_mt = mtf;
                    }
                    const __half* Ab = g_Xh  + ((size_t)mtf * KSTAGES + (fgs & 15)) * A_BLK_H;
                    const __half* Bb = g_Wth + ((size_t)(ft & 7) * KSTAGES + (fgs & 15)) * B_BLK_H;
                    mbar_expect_tx(mbF + p * 8, STG);
                    bulk_ld(sbase + p * STG,         Ab, STG_A, mbF + p * 8);
                    bulk_ld(sbase + p * STG + STG_A, Bb, STG - STG_A, mbF + p * 8);
                }
            }

            mbar_wait(mbF + (gs & 3) * 8, (uint32_t)((gs >> 2) & 1));

            const uint32_t st = sbase + (gs & 3) * STG;

            uint32_t af[2][4][4], bf[2][2][4];
            LOAD_FRAGS(st, 0, af[0], bf[0]);

            #pragma unroll
            for (int kk = 0; kk < 4; kk++) {
                const int cur = kk & 1, nxt = cur ^ 1;
                if (kk < 3) LOAD_FRAGS(st, kk + 1, af[nxt], bf[nxt]);
                #pragma unroll
                for (int mi = 0; mi < 4; mi++) {
                    #pragma unroll
                    for (int njp = 0; njp < 2; njp++) {
                        mma_f16(acc[mi][2*njp    ], af[cur][mi], &bf[cur][njp][0]);
                        mma_f16(acc[mi][2*njp + 1], af[cur][mi], &bf[cur][njp][2]);
                    }
                }
            }

            if (lane == 0) mbar_arrive(mbE + (gs & 3) * 8);
        }

        const float* hb_s  = sa;
        const float* wc_s  = sa + 128;
        const float* v_s   = sa + 256;
        const float* cov_s = sa + 384;
        #pragma unroll
        for (int mi = 0; mi < 4; mi++) {
            const int mr = wm * 64 + mi * 16 + r;
            const float cv0 = cov_s[mr], cv1 = cov_s[mr + 8];
            float s0 = 0.f, s1 = 0.f;
            #pragma unroll
            for (int nj = 0; nj < 4; nj++) {
                #pragma unroll
                for (int e = 0; e < 2; e++) {
                    const int u = wn * 32 + nj * 8 + 2 * c + e;
                    const float hb = hb_s[u], wc = wc_s[u], vv = v_s[u];
                    s0 += vv * fast_tanh(acc[mi][nj][e]     + hb + cv0 * wc);
                    s1 += vv * fast_tanh(acc[mi][nj][e + 2] + hb + cv1 * wc);
                }
            }
            s0 += __shfl_xor_sync(0xffffffffu, s0, 1);
            s0 += __shfl_xor_sync(0xffffffffu, s0, 2);
            s1 += __shfl_xor_sync(0xffffffffu, s1, 1);
            s1 += __shfl_xor_sync(0xffffffffu, s1, 2);
            if (c == 0) {
                atomicAdd(&g_score[m0 + mr],     s0);
                atomicAdd(&g_score[m0 + mr + 8], s1);
            }
        }
    }
}

// ---------------------------------------------------------------------------
// Kernel C1: softmax over S per batch; write attn + coverage; zero ctx region;
// reset g_cnt for the next (deterministic) invocation.
// ---------------------------------------------------------------------------
__global__ void softmax_cov_kernel(const float* __restrict__ prev_cov,
                                   float* __restrict__ out) {
    __shared__ float red[256];
    const int b = blockIdx.x, tid = threadIdx.x;
    const int base = b * SS;

    float l[8];
    float mx = -1e30f;
    #pragma unroll
    for (int i = 0; i < 8; i++) {
        l[i] = g_score[base + i * 256 + tid];
        mx = fmaxf(mx, l[i]);
    }
    red[tid] = mx; __syncthreads();
    for (int o = 128; o > 0; o >>= 1) {
        if (tid < o) red[tid] = fmaxf(red[tid], red[tid + o]);
        __syncthreads();
    }
    const float gmax = red[0];
    __syncthreads();

    float s = 0.f;
    #pragma unroll
    for (int i = 0; i < 8; i++) { l[i] = expf(l[i] - gmax); s += l[i]; }
    red[tid] = s; __syncthreads();
    for (int o = 128; o > 0; o >>= 1) {
        if (tid < o) red[tid] += red[tid + o];
        __syncthreads();
    }
    const float inv = 1.f / red[0];

    #pragma unroll
    for (int i = 0; i < 8; i++) {
        const int idx = base + i * 256 + tid;
        const float w = l[i] * inv;
        out[ATTN_OFF + idx] = w;
        out[COV_OFF + idx]  = w + prev_cov[idx];
    }
    for (int i = tid; i < DD; i += 256) out[CTX_OFF + b * DD + i] = 0.f;
    // reset convert counters (convert joined before this kernel)
    if (tid < 8) g_cnt[b * 8 + tid] = 0;
}

// ---------------------------------------------------------------------------
// Kernel C2: context[b,d] = sum_s attn[b,s] * X[b,s,d], blocked g_Xh.
// grid (B=32, SSPLIT=32), 128 threads. (Best config from R12/R14.)
// ---------------------------------------------------------------------------
__global__ void context_kernel(float* __restrict__ out) {
    __shared__ float aw[64];
    const int tid = threadIdx.x;          // 0..127 = (kt,ch)
    const int b = blockIdx.x;
    const int sbeg = blockIdx.y * 64;

    if (tid < 64) aw[tid] = out[ATTN_OFF + b * SS + sbeg + tid];
    __syncthreads();

    const int kt = tid >> 3, ch = tid & 7;
    const int mbase = b * SS + sbeg;
    float acc[8] = {};

    for (int s = 0; s < 64; s += 4) {
        uint4 v[4];
        #pragma unroll
        for (int q = 0; q < 4; q++) {
            const int m = mbase + s + q;
            const int mt = m >> 8, row = m & 255;
            const char* blk = (const char*)(g_Xh + ((size_t)mt * KSTAGES + kt) * A_BLK_H);
            v[q] = *(const uint4*)(blk + (row << 7) + ((ch ^ (row & 7)) << 4));
        }
        #pragma unroll
        for (int q = 0; q < 4; q++) {
            const __half2* h = (const __half2*)&v[q];
            const float w = aw[s + q];
            #pragma unroll
            for (int j = 0; j < 4; j++) {
                const float2 f = __half22float2(h[j]);
                acc[2*j]   += w * f.x;
                acc[2*j+1] += w * f.y;
            }
        }
    }
    const int d = kt * 64 + ch * 8;
    #pragma unroll
    for (int j = 0; j < 8; j++)
        atomicAdd(&out[CTX_OFF + b * DD + d + j], acc[j]);
}

// ---------------------------------------------------------------------------
extern "C" void kernel_launch(void* const* d_in, const int* in_sizes, int n_in,
                              void* d_out, int out_size) {
    int base = 3;
    if (n_in > 4 && in_sizes[3] != BS) base = 4;  // skip use_coverage scalar if present

    const float* dec      = (const float*)d_in[0];
    const float* enc      = (const float*)d_in[1];
    const float* prev_cov = (const float*)d_in[base + 0];
    const float* Ws_w     = (const float*)d_in[base + 1];
    const float* Ws_b     = (const float*)d_in[base + 2];
    const float* Wh_w     = (const float*)d_in[base + 3];
    const float* Wh_b     = (const float*)d_in[base + 4];
    const float* Wc_w     = (const float*)d_in[base + 5];
    const float* Wc_b     = (const float*)d_in[base + 6];
    const float* V_w      = (const float*)d_in[base + 7];
    // V_b unused: softmax is shift-invariant.

    float* out = (float*)d_out;

    int nsm = 148;
    cudaDeviceGetAttribute(&nsm, cudaDevAttrMultiProcessorCount, 0);

    cudaFuncSetAttribute(score_gemm_fp16,
                         cudaFuncAttributeMaxDynamicSharedMemorySize, SMEM_NEED);

    // Fork: convert X on side stream, concurrent with prep_w + GEMM on main.
    cudaStream_t s1;
    cudaStreamCreateWithFlags(&s1, cudaStreamNonBlocking);
    cudaEvent_t evFork, evJoin;
    cudaEventCreateWithFlags(&evFork, cudaEventDisableTiming);
    cudaEventCreateWithFlags(&evJoin, cudaEventDisableTiming);

    cudaEventRecord(evFork, 0);                 // legacy/default stream = capture stream
    cudaStreamWaitEvent(s1, evFork, 0);

    convert_x_kernel<<<16384, 512, 0, s1>>>(enc);           // side stream
    prep_w_kernel<<<1088, 512>>>(Ws_w, dec, Wh_w, Wh_b, Ws_b, Wc_b);
    score_gemm_fp16<<<nsm, 512, SMEM_NEED>>>(Wc_w, V_w, prev_cov);

    cudaEventRecord(evJoin, s1);
    cudaStreamWaitEvent(0, evJoin, 0);          // join before softmax (cnt reset) + context

    softmax_cov_kernel<<<BB, 256>>>(prev_cov, out);
    context_kernel<<<dim3(BB, 32), 128>>>(out);

    cudaEventDestroy(evFork);
    cudaEventDestroy(evJoin);
    cudaStreamDestroy(s1);
    (void)out_size;
}

// round 16
// speedup vs baseline: 1.1026x; 1.1026x over previous
#include <cuda_runtime.h>
#include <cuda_fp16.h>
#include <cstdint>

// Problem constants
#define BB 32
#define SS 2048
#define DD 1024
#define UU 1024
#define BS (BB*SS)            // 65536 tokens

// Output layout: context [B,D] | attn [B,S] | coverage [B,S]
#define CTX_OFF 0
#define ATTN_OFF (BB*DD)
#define COV_OFF  (BB*DD + BB*SS)

// GEMM tiling
#define BM 256
#define BN 128
#define BKH 64                         // K-chunk in halves (128B rows)
#define KSTAGES 16                     // DD / BKH
#define NTILES 2048                    // (BS/BM) * (UU/BN)
#define A_BLK_H 16384                  // halves per A tile block (256*64) = 32KB
#define B_BLK_H 8192                   // halves per B tile block (128*64) = 16KB

// Device scratch (allocation-free rule: __device__ globals)
__device__ float  g_hbias[BB*UU];          // dec@Wh + Wh_b + Ws_b + Wc_b
__device__ float  g_score[BS];             // pre-softmax scores
__device__ __half g_Xh[(size_t)BS*DD];     // enc_output fp16, tile-blocked+swizzled
__device__ __half g_Wth[UU*DD];            // Ws_w^T fp16, tile-blocked+swizzled

// ---------------------------------------------------------------------------
// helpers
// ---------------------------------------------------------------------------
__device__ __forceinline__ uint32_t smem_u32(const void* p) {
    uint32_t a;
    asm("{ .reg .u64 t; cvta.to.shared.u64 t, %1; cvt.u32.u64 %0, t; }"
        : "=r"(a) : "l"(p));
    return a;
}

__device__ __forceinline__ void mbar_init(uint32_t addr, uint32_t cnt) {
    asm volatile("mbarrier.init.shared.b64 [%0], %1;" :: "r"(addr), "r"(cnt) : "memory");
}

__device__ __forceinline__ void mbar_expect_tx(uint32_t addr, uint32_t bytes) {
    asm volatile("mbarrier.arrive.expect_tx.shared.b64 _, [%0], %1;"
                 :: "r"(addr), "r"(bytes) : "memory");
}

__device__ __forceinline__ void mbar_arrive(uint32_t addr) {
    asm volatile("mbarrier.arrive.shared.b64 _, [%0];" :: "r"(addr) : "memory");
}

__device__ __forceinline__ void mbar_wait(uint32_t addr, uint32_t parity) {
    asm volatile(
        "{\n\t.reg .pred P;\n"
        "WAIT_%=: \n\t"
        "mbarrier.try_wait.parity.acquire.cta.shared::cta.b64 P, [%0], %1, 0x989680;\n\t"
        "@P bra DONE_%=;\n\t"
        "bra WAIT_%=;\n"
        "DONE_%=: \n\t}"
        :: "r"(addr), "r"(parity) : "memory");
}

__device__ __forceinline__ void bulk_ld(uint32_t sdst, const void* gsrc,
                                        uint32_t bytes, uint32_t mbar) {
    asm volatile(
        "cp.async.bulk.shared::cta.global.mbarrier::complete_tx::bytes "
        "[%0], [%1], %2, [%3];"
        :: "r"(sdst), "l"(gsrc), "r"(bytes), "r"(mbar) : "memory");
}

__device__ __forceinline__ void fence_proxy_async_cta() {
    asm volatile("fence.proxy.async.shared::cta;" ::: "memory");
}

__device__ __forceinline__ void cp16(uint32_t saddr, const void* g) {
    asm volatile("cp.async.cg.shared.global [%0], [%1], 16;" :: "r"(saddr), "l"(g));
}

__device__ __forceinline__ void ldsm4(uint32_t* r, uint32_t addr) {
    asm volatile("ldmatrix.sync.aligned.m8n8.x4.shared.b16 {%0,%1,%2,%3}, [%4];"
                 : "=r"(r[0]), "=r"(r[1]), "=r"(r[2]), "=r"(r[3]) : "r"(addr));
}

__device__ __forceinline__ void mma_f16(float* d, const uint32_t* a, const uint32_t* b) {
    asm volatile(
        "mma.sync.aligned.m16n8k16.row.col.f32.f16.f16.f32 "
        "{%0,%1,%2,%3}, {%4,%5,%6,%7}, {%8,%9}, {%0,%1,%2,%3};\n"
        : "+f"(d[0]), "+f"(d[1]), "+f"(d[2]), "+f"(d[3])
        : "r"(a[0]), "r"(a[1]), "r"(a[2]), "r"(a[3]),
          "r"(b[0]), "r"(b[1]));
}

__device__ __forceinline__ float fast_tanh(float x) {
    float t;
    asm("tanh.approx.f32 %0, %1;" : "=f"(t) : "f"(x));
    return t;
}

// ---------------------------------------------------------------------------
// Mega prep kernel: blocks [0,1024) transpose Ws, [1024,1088) hbias+score0,
// [1088,17472) convert X. All 512 threads.
// ---------------------------------------------------------------------------
__global__ void __launch_bounds__(512)
prep_kernel(const float* __restrict__ X,
            const float* __restrict__ W,
            const float* __restrict__ dec,
            const float* __restrict__ Whw,
            const float* __restrict__ Whb,
            const float* __restrict__ Wsb,
            const float* __restrict__ Wcb) {
    __shared__ float sbuf[1184];
    const int bid = blockIdx.x;
    const int tid = threadIdx.x;

    if (bid < 1024) {
        // ----- transpose+convert Ws_w [D,U] -> g_Wth tile-blocked swizzled
        float (*t)[33] = (float(*)[33])sbuf;
        const int tx = tid & 31, ty = tid >> 5;          // ty 0..15
        const int bx = (bid & 31) * 32;                   // u base
        const int by = (bid >> 5) * 32;                   // d base
        #pragma unroll
        for (int j = 0; j < 2; j++)
            t[ty + j * 16][tx] = W[(size_t)(by + ty + j * 16) * UU + bx + tx];
        __syncthreads();
        #pragma unroll
        for (int j = 0; j < 2; j++) {
            const int u = bx + ty + j * 16;
            const int d = by + tx;
            const int nt = u >> 7, rowB = u & 127;
            const int kt = d >> 6, ch = (d & 63) >> 3, pos = d & 7;
            char* blk = (char*)(g_Wth + ((size_t)nt * KSTAGES + kt) * B_BLK_H);
            *(__half*)(blk + (rowB << 7) + ((ch ^ (rowB & 7)) << 4) + pos * 2) =
                __float2half(t[tx][ty + j * 16]);
        }
    } else if (bid < 1088) {
        // ----- hbias + zero g_score
        float* dh = sbuf;
        const int lb = bid - 1024;
        const int b = lb >> 1;
        const int u = (lb & 1) * 512 + tid;
        dh[tid] = dec[b * DD + tid];
        dh[tid + 512] = dec[b * DD + tid + 512];
        __syncthreads();

        float a0 = 0.f, a1 = 0.f, a2 = 0.f, a3 = 0.f;
        #pragma unroll 4
        for (int d = 0; d < DD; d += 4) {
            a0 += dh[d+0] * Whw[(size_t)(d+0)*UU + u];
            a1 += dh[d+1] * Whw[(size_t)(d+1)*UU + u];
            a2 += dh[d+2] * Whw[(size_t)(d+2)*UU + u];
            a3 += dh[d+3] * Whw[(size_t)(d+3)*UU + u];
        }
        g_hbias[b*UU + u] = (a0 + a1) + (a2 + a3) + Whb[u] + Wsb[u] + Wcb[u];

        const int gid = lb * 512 + tid;
        g_score[gid] = 0.f;
        g_score[gid + 32768] = 0.f;
    } else {
        // ----- convert enc fp32 -> fp16 tile-blocked swizzled
        const size_t i = (size_t)(bid - 1088) * 512 + tid;
        const int m  = (int)(i >> 7);
        const int cg = (int)(i & 127);
        const int kt = cg >> 3;
        const int ch = cg & 7;
        const int mt = m >> 8;
        const int row = m & 255;

        const float4* src = (const float4*)(X + (size_t)m * DD + kt * 64 + ch * 8);
        const float4 f0 = src[0];
        const float4 f1 = src[1];
        __half2 h0 = __float22half2_rn(make_float2(f0.x, f0.y));
        __half2 h1 = __float22half2_rn(make_float2(f0.z, f0.w));
        __half2 h2 = __float22half2_rn(make_float2(f1.x, f1.y));
        __half2 h3 = __float22half2_rn(make_float2(f1.z, f1.w));
        uint4 o;
        o.x = *(uint32_t*)&h0; o.y = *(uint32_t*)&h1;
        o.z = *(uint32_t*)&h2; o.w = *(uint32_t*)&h3;

        char* blk = (char*)(g_Xh + ((size_t)mt * KSTAGES + kt) * A_BLK_H);
        *(uint4*)(blk + (row << 7) + ((ch ^ (row & 7)) << 4)) = o;
    }
}

// ---------------------------------------------------------------------------
// Kernel B: PERSISTENT fp16 mma.sync fused score GEMM.
// grid = #SMs; pipeline runs continuously across tile boundaries.
// ---------------------------------------------------------------------------
#define NST 4
#define STG 49152                      // 32KB A + 16KB B
#define STG_A 32768
#define OFF_SMALL (NST*STG)            // 196608; 2 x 640 floats
#define OFF_MBAR  (OFF_SMALL + 5120)   // 4 full mbarriers
#define OFF_MBARE (OFF_MBAR + 32)      // 4 empty mbarriers
#define SMEM_NEED (OFF_MBARE + 32)     // 201792

__global__ void __launch_bounds__(512, 1)
score_gemm_fp16(const float* __restrict__ Wcw,
                const float* __restrict__ Vw,
                const float* __restrict__ cov) {
    extern __shared__ char sm[];
    const int tid  = threadIdx.x;
    const int lane = tid & 31;
    const int wid  = tid >> 5;
    const int wm   = wid >> 2;        // 0..3
    const int wn   = wid & 3;         // 0..3
    const int r    = lane >> 2;       // 0..7
    const int c    = lane & 3;        // 0..3

    const uint32_t sbase = smem_u32(sm);
    const uint32_t mbF   = sbase + OFF_MBAR;
    const uint32_t mbE   = sbase + OFF_MBARE;
    const int grid = gridDim.x;
    const int ntiles = (NTILES - blockIdx.x + grid - 1) / grid;
    const int total_gs = ntiles * KSTAGES;

    if (tid == 0) {
        #pragma unroll
        for (int p = 0; p < NST; p++) {
            mbar_init(mbF + p * 8, 1);    // full: tx-based
            mbar_init(mbE + p * 8, 16);   // empty: one arrive per warp
        }
    }

    float* small0 = (float*)(sm + OFF_SMALL);

    {
        const int t0 = blockIdx.x;
        const int m0 = (t0 >> 3) * BM, n0 = (t0 & 7) * BN, b = m0 >> 11;
        if (tid < 128) {
            small0[tid]       = g_hbias[b * UU + n0 + tid];
            small0[128 + tid] = Wcw[n0 + tid];
            small0[256 + tid] = Vw[n0 + tid];
        } else if (tid < 384) {
            small0[384 + tid - 128] = cov[m0 + tid - 128];
        }
    }
    __syncthreads();
    fence_proxy_async_cta();

    if (tid == 0) {
        const int t0 = blockIdx.x;
        const __half* Ab = g_Xh  + (size_t)(t0 >> 3) * KSTAGES * A_BLK_H;
        const __half* Bb = g_Wth + (size_t)(t0 & 7)  * KSTAGES * B_BLK_H;
        #pragma unroll
        for (int p = 0; p < 3; p++) {
            mbar_expect_tx(mbF + p * 8, STG);
            bulk_ld(sbase + p * STG,         Ab + (size_t)p * A_BLK_H, STG_A, mbF + p * 8);
            bulk_ld(sbase + p * STG + STG_A, Bb + (size_t)p * B_BLK_H, STG - STG_A, mbF + p * 8);
        }
    }

    const uint32_t slane = lane & 7;
    const uint32_t ahi   = lane >> 4;
    const uint32_t bbit  = (lane >> 3) & 1;
    uint32_t arow_off[4], brow_off[2];
    #pragma unroll
    for (int mi = 0; mi < 4; mi++)
        arow_off[mi] = (uint32_t)((wm * 64 + mi * 16 + (lane & 15)) << 7);
    #pragma unroll
    for (int njp = 0; njp < 2; njp++)
        brow_off[njp] = (uint32_t)(((wn * 32 + njp * 16 + slane + (ahi << 3)) << 7)
                                   + STG_A);

    #define LOAD_FRAGS(ST_, KK_, AF_, BF_) do {                               \
        const uint32_t xa_ = ((((KK_) << 1) + ahi)  ^ slane) << 4;            \
        const uint32_t xb_ = ((((KK_) << 1) + bbit) ^ slane) << 4;            \
        _Pragma("unroll")                                                     \
        for (int mi_ = 0; mi_ < 4; mi_++)                                     \
            ldsm4(AF_[mi_], (ST_) + arow_off[mi_] + xa_);                     \
        _Pragma("unroll")                                                     \
        for (int nj_ = 0; nj_ < 2; nj_++)                                     \
            ldsm4(BF_[nj_], (ST_) + brow_off[nj_] + xb_);                     \
    } while (0)

    int gs = 0;
    for (int tt = 0; tt < ntiles; tt++) {
        const int tile = blockIdx.x + tt * grid;
        const int m0 = (tile >> 3) * BM;
        const int n0 = (tile & 7) * BN;
        const int b  = m0 >> 11;
        float* sa = small0 + (tt & 1) * 640;

        if (tt > 0) {
            if (tid < 128) {
                sa[tid]       = g_hbias[b * UU + n0 + tid];
                sa[128 + tid] = Wcw[n0 + tid];
                sa[256 + tid] = Vw[n0 + tid];
            } else if (tid < 384) {
                sa[384 + tid - 128] = cov[m0 + tid - 128];
            }
        }

        float acc[4][4][4] = {};

        for (int s = 0; s < KSTAGES; s++, gs++) {
            if (tid == 0) {
                const int fgs = gs + 3;
                if (fgs < total_gs) {
                    const int p = fgs & 3;
                    if (gs >= 1)
                        mbar_wait(mbE + p * 8, (uint32_t)(((gs - 1) >> 2) & 1));
                    const int ft = blockIdx.x + (fgs >> 4) * grid;
                    const __half* Ab = g_Xh  + ((size_t)(ft >> 3) * KSTAGES + (fgs & 15)) * A_BLK_H;
                    const __half* Bb = g_Wth + ((size_t)(ft & 7)  * KSTAGES + (fgs & 15)) * B_BLK_H;
                    mbar_expect_tx(mbF + p * 8, STG);
                    bulk_ld(sbase + p * STG,         Ab, STG_A, mbF + p * 8);
                    bulk_ld(sbase + p * STG + STG_A, Bb, STG - STG_A, mbF + p * 8);
                }
            }

            mbar_wait(mbF + (gs & 3) * 8, (uint32_t)((gs >> 2) & 1));

            const uint32_t st = sbase + (gs & 3) * STG;

            uint32_t af[2][4][4], bf[2][2][4];
            LOAD_FRAGS(st, 0, af[0], bf[0]);

            #pragma unroll
            for (int kk = 0; kk < 4; kk++) {
                const int cur = kk & 1, nxt = cur ^ 1;
                if (kk < 3) LOAD_FRAGS(st, kk + 1, af[nxt], bf[nxt]);
                #pragma unroll
                for (int mi = 0; mi < 4; mi++) {
                    #pragma unroll
                    for (int njp = 0; njp < 2; njp++) {
                        mma_f16(acc[mi][2*njp    ], af[cur][mi], &bf[cur][njp][0]);
                        mma_f16(acc[mi][2*njp + 1], af[cur][mi], &bf[cur][njp][2]);
                    }
                }
            }

            if (lane == 0) mbar_arrive(mbE + (gs & 3) * 8);
        }

        const float* hb_s  = sa;
        const float* wc_s  = sa + 128;
        const float* v_s   = sa + 256;
        const float* cov_s = sa + 384;
        #pragma unroll
        for (int mi = 0; mi < 4; mi++) {
            const int mr = wm * 64 + mi * 16 + r;
            const float cv0 = cov_s[mr], cv1 = cov_s[mr + 8];
            float s0 = 0.f, s1 = 0.f;
            #pragma unroll
            for (int nj = 0; nj < 4; nj++) {
                #pragma unroll
                for (int e = 0; e < 2; e++) {
                    const int u = wn * 32 + nj * 8 + 2 * c + e;
                    const float hb = hb_s[u], wc = wc_s[u], vv = v_s[u];
                    s0 += vv * fast_tanh(acc[mi][nj][e]     + hb + cv0 * wc);
                    s1 += vv * fast_tanh(acc[mi][nj][e + 2] + hb + cv1 * wc);
                }
            }
            s0 += __shfl_xor_sync(0xffffffffu, s0, 1);
            s0 += __shfl_xor_sync(0xffffffffu, s0, 2);
            s1 += __shfl_xor_sync(0xffffffffu, s1, 1);
            s1 += __shfl_xor_sync(0xffffffffu, s1, 2);
            if (c == 0) {
                atomicAdd(&g_score[m0 + mr],     s0);
                atomicAdd(&g_score[m0 + mr + 8], s1);
            }
        }
    }
}

// ---------------------------------------------------------------------------
// Kernel C1: softmax over S per batch; write attn + coverage; zero ctx region.
// ---------------------------------------------------------------------------
__global__ void softmax_cov_kernel(const float* __restrict__ prev_cov,
                                   float* __restrict__ out) {
    __shared__ float red[256];
    const int b = blockIdx.x, tid = threadIdx.x;
    const int base = b * SS;

    float l[8];
    float mx = -1e30f;
    #pragma unroll
    for (int i = 0; i < 8; i++) {
        l[i] = g_score[base + i * 256 + tid];
        mx = fmaxf(mx, l[i]);
    }
    red[tid] = mx; __syncthreads();
    for (int o = 128; o > 0; o >>= 1) {
        if (tid < o) red[tid] = fmaxf(red[tid], red[tid + o]);
        __syncthreads();
    }
    const float gmax = red[0];
    __syncthreads();

    float s = 0.f;
    #pragma unroll
    for (int i = 0; i < 8; i++) { l[i] = expf(l[i] - gmax); s += l[i]; }
    red[tid] = s; __syncthreads();
    for (int o = 128; o > 0; o >>= 1) {
        if (tid < o) red[tid] += red[tid + o];
        __syncthreads();
    }
    const float inv = 1.f / red[0];

    #pragma unroll
    for (int i = 0; i < 8; i++) {
        const int idx = base + i * 256 + tid;
        const float w = l[i] * inv;
        out[ATTN_OFF + idx] = w;
        out[COV_OFF + idx]  = w + prev_cov[idx];
    }
    for (int i = tid; i < DD; i += 256) out[CTX_OFF + b * DD + i] = 0.f;
}

// ---------------------------------------------------------------------------
// Kernel C2: context[b,d] = sum_s attn[b,s] * X[b,s,d], blocked g_Xh.
// cp.async double-buffered smem staging: true MLP (async queue holds state,
// no dest-register chaining). Each thread consumes ONLY its own staged
// chunks -> no in-loop __syncthreads. grid (B=32, SSPLIT=32), 128 threads.
// ---------------------------------------------------------------------------
__global__ void context_kernel(float* __restrict__ out) {
    __shared__ float aw[64];
    __shared__ __align__(16) char buf[2][16384];   // 128 thr x 8 tok x 16B
    const int tid = threadIdx.x;          // 0..127 = (kt,ch)
    const int b = blockIdx.x;
    const int sbeg = blockIdx.y * 64;

    if (tid < 64) aw[tid] = out[ATTN_OFF + b * SS + sbeg + tid];
    __syncthreads();

    const int kt = tid >> 3, ch = tid & 7;
    const int mbase = b * SS + sbeg;
    const uint32_t sbuf = smem_u32(buf);
    float acc[8] = {};

    // Issue group G (8 tokens) into buffer P: 8 cp.async per thread.
    #define CTX_ISSUE(G, P) do {                                              \
        _Pragma("unroll")                                                     \
        for (int q_ = 0; q_ < 8; q_++) {                                      \
            const int m_ = mbase + (G) * 8 + q_;                              \
            const int mt_ = m_ >> 8, row_ = m_ & 255;                         \
            const char* g_ = (const char*)(g_Xh +                            \
                ((size_t)mt_ * KSTAGES + kt) * A_BLK_H)                       \
                + (row_ << 7) + ((ch ^ (row_ & 7)) << 4);                     \
            cp16(sbuf + (P) * 16384 + (((q_ << 7) + tid) << 4), g_);          \
        }                                                                     \
        asm volatile("cp.async.commit_group;" ::: "memory");                  \
    } while (0)

    CTX_ISSUE(0, 0);
    for (int g8 = 0; g8 < 8; g8++) {
        if (g8 < 7) {
            CTX_ISSUE(g8 + 1, (g8 + 1) & 1);
            asm volatile("cp.async.wait_group 1;" ::: "memory");
        } else {
            asm volatile("cp.async.wait_group 0;" ::: "memory");
        }
        #pragma unroll
        for (int q = 0; q < 8; q++) {
            const uint4 v = *(const uint4*)(buf[g8 & 1] + (((q << 7) + tid) << 4));
            const __half2* h = (const __half2*)&v;
            const float w = aw[g8 * 8 + q];
            #pragma unroll
            for (int j = 0; j < 4; j++) {
                const float2 f = __half22float2(h[j]);
                acc[2*j]   += w * f.x;
                acc[2*j+1] += w * f.y;
            }
        }
    }
    const int d = kt * 64 + ch * 8;
    #pragma unroll
    for (int j = 0; j < 8; j++)
        atomicAdd(&out[CTX_OFF + b * DD + d + j], acc[j]);
}

// ---------------------------------------------------------------------------
extern "C" void kernel_launch(void* const* d_in, const int* in_sizes, int n_in,
                              void* d_out, int out_size) {
    int base = 3;
    if (n_in > 4 && in_sizes[3] != BS) base = 4;  // skip use_coverage scalar if present

    const float* dec      = (const float*)d_in[0];
    const float* enc      = (const float*)d_in[1];
    const float* prev_cov = (const float*)d_in[base + 0];
    const float* Ws_w     = (const float*)d_in[base + 1];
    const float* Ws_b     = (const float*)d_in[base + 2];
    const float* Wh_w     = (const float*)d_in[base + 3];
    const float* Wh_b     = (const float*)d_in[base + 4];
    const float* Wc_w     = (const float*)d_in[base + 5];
    const float* Wc_b     = (const float*)d_in[base + 6];
    const float* V_w      = (const float*)d_in[base + 7];
    // V_b unused: softmax is shift-invariant.

    float* out = (float*)d_out;

    int nsm = 148;
    cudaDeviceGetAttribute(&nsm, cudaDevAttrMultiProcessorCount, 0);

    cudaFuncSetAttribute(score_gemm_fp16,
                         cudaFuncAttributeMaxDynamicSharedMemorySize, SMEM_NEED);

    prep_kernel<<<17472, 512>>>(enc, Ws_w, dec, Wh_w, Wh_b, Ws_b, Wc_b);
    score_gemm_fp16<<<nsm, 512, SMEM_NEED>>>(Wc_w, V_w, prev_cov);
    softmax_cov_kernel<<<BB, 256>>>(prev_cov, out);
    context_kernel<<<dim3(BB, 32), 128>>>(out);
    (void)out_size;
}